// round 1
// baseline (speedup 1.0000x reference)
#include <cuda_runtime.h>
#include <math.h>
#include <math_constants.h>

// Fixed problem geometry (GELU2_5892695130299): x (4,4096,4096) f32, emas (256,4096) f32.
#define DD       4096      // feature dim
#define KP       256       // number of prototypes
#define MT       64        // GEMM row tile
#define KT       32        // GEMM k chunk
#define EPS_NRM  1e-12f
#define SQ2PI    0.7978845608028654f

// ---- device scratch (no allocations allowed) ----
__device__ float g_pnorm[KP * DD];        // normalized prototypes (4 MB, L2-resident)
__device__ float g_scale[32768];          // per-row output scale
__device__ float g_partials[128 * DD];    // column-sum partials (deterministic)
__device__ float g_xsum[DD];              // column sums of x
__device__ float g_dots[KP];              // p_norm . x_sum

__device__ __forceinline__ float sigmoidf_(float v) { return 1.0f / (1.0f + expf(-v)); }

__device__ __forceinline__ float gelu_tanh(float y) {
    return 0.5f * y * (1.0f + tanhf(SQ2PI * (y + 0.044715f * y * y * y)));
}

// ---------------------------------------------------------------------------
// 1) Normalize prototypes: g_pnorm[k] = emas[k] / max(||emas[k]||, eps)
// ---------------------------------------------------------------------------
__global__ void k_proto_norm(const float* __restrict__ emas) {
    __shared__ float red[256];
    int k = blockIdx.x;
    const float* row = emas + (size_t)k * DD;
    float s = 0.f;
    for (int d = threadIdx.x; d < DD; d += 256) { float v = row[d]; s += v * v; }
    red[threadIdx.x] = s; __syncthreads();
    for (int off = 128; off > 0; off >>= 1) {
        if (threadIdx.x < off) red[threadIdx.x] += red[threadIdx.x + off];
        __syncthreads();
    }
    float inv = 1.0f / fmaxf(sqrtf(red[0]), EPS_NRM);
    for (int d = threadIdx.x; d < DD; d += 256)
        g_pnorm[(size_t)k * DD + d] = row[d] * inv;
}

// ---------------------------------------------------------------------------
// 2) Column sums of x (deterministic two-stage; no float atomics)
// ---------------------------------------------------------------------------
__global__ void k_colsum_partial(const float* __restrict__ x, int rows_per) {
    int col = blockIdx.x * 256 + threadIdx.x;
    int rb  = blockIdx.y;
    const float* p = x + (size_t)rb * rows_per * DD + col;
    float s = 0.f;
    #pragma unroll 4
    for (int r = 0; r < rows_per; r++) s += p[(size_t)r * DD];
    g_partials[(size_t)rb * DD + col] = s;
}

__global__ void k_colsum_reduce(int nrb) {
    int col = blockIdx.x * 256 + threadIdx.x;
    float s = 0.f;
    for (int rb = 0; rb < nrb; rb++) s += g_partials[(size_t)rb * DD + col];
    g_xsum[col] = s;
}

// ---------------------------------------------------------------------------
// 3) dots[k] = p_norm[k] . x_sum   (argmax-equivalent to reference: positive scaling)
// ---------------------------------------------------------------------------
__global__ void k_dots(int Kp) {
    int warp = threadIdx.x >> 5, lane = threadIdx.x & 31;
    int k = blockIdx.x * 8 + warp;
    if (k >= Kp) return;
    const float* pr = g_pnorm + (size_t)k * DD;
    float s = 0.f;
    for (int d = lane; d < DD; d += 32) s += pr[d] * g_xsum[d];
    #pragma unroll
    for (int off = 16; off; off >>= 1) s += __shfl_xor_sync(0xffffffffu, s, off);
    if (lane == 0) g_dots[k] = s;
}

// ---------------------------------------------------------------------------
// 4) Copy emas -> output emas region (float4)
// ---------------------------------------------------------------------------
__global__ void k_copy4(const float4* __restrict__ src, float4* __restrict__ dst, int n4) {
    int i = blockIdx.x * blockDim.x + threadIdx.x;
    if (i < n4) dst[i] = src[i];
}

// ---------------------------------------------------------------------------
// 5) argmax(dots) + EMA row update (first-max tie-break like jnp.argmax)
// ---------------------------------------------------------------------------
__global__ void k_update(const float* __restrict__ emas,
                         const float* __restrict__ logit_decay,
                         float* __restrict__ out_emas, int BT, int Kp) {
    __shared__ float bv[256];
    __shared__ int   bi[256];
    int t = threadIdx.x;
    bv[t] = (t < Kp) ? g_dots[t] : -CUDART_INF_F;
    bi[t] = t;
    __syncthreads();
    for (int off = 128; off > 0; off >>= 1) {
        if (t < off) {
            if (bv[t + off] > bv[t] || (bv[t + off] == bv[t] && bi[t + off] < bi[t])) {
                bv[t] = bv[t + off]; bi[t] = bi[t + off];
            }
        }
        __syncthreads();
    }
    int ks = bi[0];
    float dd = sigmoidf_(logit_decay[0]);
    float invBT = 1.0f / (float)BT;
    for (int d = t; d < DD; d += 256) {
        float mean = g_xsum[d] * invBT;
        out_emas[(size_t)ks * DD + d] = dd * emas[(size_t)ks * DD + d] + (1.0f - dd) * mean;
    }
}

// ---------------------------------------------------------------------------
// 6) Fused sim-GEMM (M=BT, N=256, K=4096) + row norms + max_k + scale
//    Tile: 64 rows x 256 cols per CTA, k-chunks of 32, transposed padded smem.
// ---------------------------------------------------------------------------
__global__ __launch_bounds__(256, 2) void k_sim(const float* __restrict__ x,
                                                const float* __restrict__ log_tau,
                                                const float* __restrict__ log_blend,
                                                const float* __restrict__ logit_decay) {
    __shared__ float xs[KT][MT + 1];        // [32][65]
    __shared__ float ps[KT][KP + 1];        // [32][257]
    __shared__ float rnorm[MT];

    int tid = threadIdx.x;
    int tx = tid & 15, ty = tid >> 4;
    int row0 = blockIdx.x * MT;

    float acc[4][16];
    #pragma unroll
    for (int i = 0; i < 4; i++)
        #pragma unroll
        for (int j = 0; j < 16; j++) acc[i][j] = 0.f;

    int lkk = tid & 31;        // k-offset this thread loads
    int lr  = tid >> 5;        // 0..7
    float nrm[8];
    #pragma unroll
    for (int i = 0; i < 8; i++) nrm[i] = 0.f;

    for (int k0 = 0; k0 < DD; k0 += KT) {
        __syncthreads();
        // x tile: rows lr + 8i, col k0+lkk (coalesced global, conflict-free smem store)
        #pragma unroll
        for (int i = 0; i < 8; i++) {
            int r = lr + i * 8;
            float v = x[(size_t)(row0 + r) * DD + k0 + lkk];
            xs[lkk][r] = v;
            nrm[i] += v * v;   // fold row-sumsq into the load
        }
        // p tile: 256 cols x 32 k
        #pragma unroll
        for (int i = 0; i < 32; i++) {
            int c = lr + i * 8;
            ps[lkk][c] = g_pnorm[(size_t)c * DD + k0 + lkk];
        }
        __syncthreads();
        #pragma unroll
        for (int kk = 0; kk < KT; kk++) {
            float xr[4];
            #pragma unroll
            for (int i = 0; i < 4; i++) xr[i] = xs[kk][ty + 16 * i];
            #pragma unroll
            for (int j = 0; j < 16; j++) {
                float pv = ps[kk][tx + 16 * j];
                #pragma unroll
                for (int i = 0; i < 4; i++) acc[i][j] += xr[i] * pv;
            }
        }
    }

    // Row sumsq: warp lr holds all 32 k-offsets for rows lr+8i -> warp reduce.
    #pragma unroll
    for (int i = 0; i < 8; i++) {
        float v = nrm[i];
        #pragma unroll
        for (int off = 16; off; off >>= 1) v += __shfl_xor_sync(0xffffffffu, v, off);
        if ((tid & 31) == 0) rnorm[lr + i * 8] = v;
    }
    __syncthreads();

    float tau = expf(log_tau[0]);
    float ad  = sigmoidf_(log_blend[0]) * sigmoidf_(logit_decay[0]);

    // Per-row max over 256 cols; lane layout: lane = (ty&1)*16 + tx, so xor<16 mixes tx only.
    #pragma unroll
    for (int i = 0; i < 4; i++) {
        float m = acc[i][0];
        #pragma unroll
        for (int j = 1; j < 16; j++) m = fmaxf(m, acc[i][j]);
        #pragma unroll
        for (int off = 1; off < 16; off <<= 1) m = fmaxf(m, __shfl_xor_sync(0xffffffffu, m, off));
        if (tx == 0) {
            int r = ty + 16 * i;
            float inv = 1.0f / fmaxf(sqrtf(rnorm[r]), EPS_NRM);
            float sim = m * inv;                      // norms > 0: max(acc)/n == max(acc/n)
            float nov = expf(-tau * sim);
            g_scale[row0 + r] = 1.0f - ad + ad * nov;
        }
    }
}

// ---------------------------------------------------------------------------
// 7) GELU pass: out = gelu(x * scale[row]), float4 vectorized
// ---------------------------------------------------------------------------
__global__ void k_gelu(const float4* __restrict__ x4, float4* __restrict__ o4, int n4) {
    int i = blockIdx.x * blockDim.x + threadIdx.x;
    if (i >= n4) return;
    float4 v = x4[i];
    float s = g_scale[i >> 10];   // DD/4 = 1024 float4 per row
    v.x = gelu_tanh(v.x * s);
    v.y = gelu_tanh(v.y * s);
    v.z = gelu_tanh(v.z * s);
    v.w = gelu_tanh(v.w * s);
    o4[i] = v;
}

// ---------------------------------------------------------------------------
extern "C" void kernel_launch(void* const* d_in, const int* in_sizes, int n_in,
                              void* d_out, int out_size) {
    const float* x           = (const float*)d_in[0];
    const float* emas        = (const float*)d_in[1];
    const float* log_tau     = (const float*)d_in[2];
    const float* log_blend   = (const float*)d_in[3];
    const float* logit_decay = (const float*)d_in[4];

    int BT = in_sizes[0] / DD;      // 16384
    int Kp = in_sizes[1] / DD;      // 256
    float* out_x    = (float*)d_out;
    float* out_emas = (float*)d_out + (size_t)in_sizes[0];

    // prototypes
    k_proto_norm<<<Kp, 256>>>(emas);

    // deterministic column sums
    int nrb = BT / 256;             // 64 row blocks
    dim3 gcs(DD / 256, nrb);
    k_colsum_partial<<<gcs, 256>>>(x, 256);
    k_colsum_reduce<<<DD / 256, 256>>>(nrb);

    // argmax side-path + emas output
    k_dots<<<(Kp + 7) / 8, 256>>>(Kp);
    int n4e = in_sizes[1] / 4;
    k_copy4<<<(n4e + 255) / 256, 256>>>((const float4*)emas, (float4*)out_emas, n4e);
    k_update<<<1, 256>>>(emas, logit_decay, out_emas, BT, Kp);

    // main fused GEMM -> per-row scale
    k_sim<<<BT / MT, 256>>>(x, log_tau, log_blend, logit_decay);

    // elementwise gelu
    int n4x = in_sizes[0] / 4;
    k_gelu<<<(n4x + 255) / 256, 256>>>((const float4*)x, (float4*)out_x, n4x);
}

// round 2
// speedup vs baseline: 1.0040x; 1.0040x over previous
#include <cuda_runtime.h>
#include <math.h>
#include <math_constants.h>

// Fixed problem geometry (GELU2_5892695130299): x (4,4096,4096) f32, emas (256,4096) f32.
#define DD       4096      // feature dim
#define KP       256       // number of prototypes
#define MT       64        // GEMM row tile
#define KT       32        // GEMM k chunk
#define EPS_NRM  1e-12f
#define SQ2PI    0.7978845608028654f

// ---- device scratch (no allocations allowed) ----
__device__ float g_pnorm[KP * DD];        // normalized prototypes (4 MB, L2-resident)
__device__ float g_scale[32768];          // per-row output scale
__device__ float g_partials[128 * DD];    // column-sum partials (deterministic)
__device__ float g_xsum[DD];              // column sums of x
__device__ float g_dots[KP];              // p_norm . x_sum

__device__ __forceinline__ float sigmoidf_(float v) { return 1.0f / (1.0f + expf(-v)); }

__device__ __forceinline__ float gelu_tanh(float y) {
    return 0.5f * y * (1.0f + tanhf(SQ2PI * (y + 0.044715f * y * y * y)));
}

// ---------------------------------------------------------------------------
// 1) Normalize prototypes: g_pnorm[k] = emas[k] / max(||emas[k]||, eps)
// ---------------------------------------------------------------------------
__global__ void k_proto_norm(const float* __restrict__ emas) {
    __shared__ float red[256];
    int k = blockIdx.x;
    const float* row = emas + (size_t)k * DD;
    float s = 0.f;
    for (int d = threadIdx.x; d < DD; d += 256) { float v = row[d]; s += v * v; }
    red[threadIdx.x] = s; __syncthreads();
    for (int off = 128; off > 0; off >>= 1) {
        if (threadIdx.x < off) red[threadIdx.x] += red[threadIdx.x + off];
        __syncthreads();
    }
    float inv = 1.0f / fmaxf(sqrtf(red[0]), EPS_NRM);
    for (int d = threadIdx.x; d < DD; d += 256)
        g_pnorm[(size_t)k * DD + d] = row[d] * inv;
}

// ---------------------------------------------------------------------------
// 2) Column sums of x (deterministic two-stage; no float atomics)
// ---------------------------------------------------------------------------
__global__ void k_colsum_partial(const float* __restrict__ x, int rows_per) {
    int col = blockIdx.x * 256 + threadIdx.x;
    int rb  = blockIdx.y;
    const float* p = x + (size_t)rb * rows_per * DD + col;
    float s = 0.f;
    #pragma unroll 4
    for (int r = 0; r < rows_per; r++) s += p[(size_t)r * DD];
    g_partials[(size_t)rb * DD + col] = s;
}

__global__ void k_colsum_reduce(int nrb) {
    int col = blockIdx.x * 256 + threadIdx.x;
    float s = 0.f;
    for (int rb = 0; rb < nrb; rb++) s += g_partials[(size_t)rb * DD + col];
    g_xsum[col] = s;
}

// ---------------------------------------------------------------------------
// 3) dots[k] = p_norm[k] . x_sum   (argmax-equivalent to reference: positive scaling)
// ---------------------------------------------------------------------------
__global__ void k_dots(int Kp) {
    int warp = threadIdx.x >> 5, lane = threadIdx.x & 31;
    int k = blockIdx.x * 8 + warp;
    if (k >= Kp) return;
    const float* pr = g_pnorm + (size_t)k * DD;
    float s = 0.f;
    for (int d = lane; d < DD; d += 32) s += pr[d] * g_xsum[d];
    #pragma unroll
    for (int off = 16; off; off >>= 1) s += __shfl_xor_sync(0xffffffffu, s, off);
    if (lane == 0) g_dots[k] = s;
}

// ---------------------------------------------------------------------------
// 4) Copy emas -> output emas region (float4)
// ---------------------------------------------------------------------------
__global__ void k_copy4(const float4* __restrict__ src, float4* __restrict__ dst, int n4) {
    int i = blockIdx.x * blockDim.x + threadIdx.x;
    if (i < n4) dst[i] = src[i];
}

// ---------------------------------------------------------------------------
// 5) argmax(dots) + EMA row update (first-max tie-break like jnp.argmax)
// ---------------------------------------------------------------------------
__global__ void k_update(const float* __restrict__ emas,
                         const float* __restrict__ logit_decay,
                         float* __restrict__ out_emas, int BT, int Kp) {
    __shared__ float bv[256];
    __shared__ int   bi[256];
    int t = threadIdx.x;
    bv[t] = (t < Kp) ? g_dots[t] : -CUDART_INF_F;
    bi[t] = t;
    __syncthreads();
    for (int off = 128; off > 0; off >>= 1) {
        if (t < off) {
            if (bv[t + off] > bv[t] || (bv[t + off] == bv[t] && bi[t + off] < bi[t])) {
                bv[t] = bv[t + off]; bi[t] = bi[t + off];
            }
        }
        __syncthreads();
    }
    int ks = bi[0];
    float dd = sigmoidf_(logit_decay[0]);
    float invBT = 1.0f / (float)BT;
    for (int d = t; d < DD; d += 256) {
        float mean = g_xsum[d] * invBT;
        out_emas[(size_t)ks * DD + d] = dd * emas[(size_t)ks * DD + d] + (1.0f - dd) * mean;
    }
}

// ---------------------------------------------------------------------------
// 6) Fused sim-GEMM (M=BT, N=256, K=4096) + row norms + max_k + scale
//    Tile: 64 rows x 256 cols per CTA, k-chunks of 32, transposed padded smem.
// ---------------------------------------------------------------------------
__global__ __launch_bounds__(256, 2) void k_sim(const float* __restrict__ x,
                                                const float* __restrict__ log_tau,
                                                const float* __restrict__ log_blend,
                                                const float* __restrict__ logit_decay) {
    __shared__ float xs[KT][MT + 1];        // [32][65]
    __shared__ float ps[KT][KP + 1];        // [32][257]
    __shared__ float rnorm[MT];

    int tid = threadIdx.x;
    int tx = tid & 15, ty = tid >> 4;
    int row0 = blockIdx.x * MT;

    float acc[4][16];
    #pragma unroll
    for (int i = 0; i < 4; i++)
        #pragma unroll
        for (int j = 0; j < 16; j++) acc[i][j] = 0.f;

    int lkk = tid & 31;        // k-offset this thread loads
    int lr  = tid >> 5;        // 0..7
    float nrm[8];
    #pragma unroll
    for (int i = 0; i < 8; i++) nrm[i] = 0.f;

    for (int k0 = 0; k0 < DD; k0 += KT) {
        __syncthreads();
        // x tile: rows lr + 8i, col k0+lkk (coalesced global, conflict-free smem store)
        #pragma unroll
        for (int i = 0; i < 8; i++) {
            int r = lr + i * 8;
            float v = x[(size_t)(row0 + r) * DD + k0 + lkk];
            xs[lkk][r] = v;
            nrm[i] += v * v;   // fold row-sumsq into the load
        }
        // p tile: 256 cols x 32 k
        #pragma unroll
        for (int i = 0; i < 32; i++) {
            int c = lr + i * 8;
            ps[lkk][c] = g_pnorm[(size_t)c * DD + k0 + lkk];
        }
        __syncthreads();
        #pragma unroll
        for (int kk = 0; kk < KT; kk++) {
            float xr[4];
            #pragma unroll
            for (int i = 0; i < 4; i++) xr[i] = xs[kk][ty + 16 * i];
            #pragma unroll
            for (int j = 0; j < 16; j++) {
                float pv = ps[kk][tx + 16 * j];
                #pragma unroll
                for (int i = 0; i < 4; i++) acc[i][j] += xr[i] * pv;
            }
        }
    }

    // Row sumsq: warp lr holds all 32 k-offsets for rows lr+8i -> warp reduce.
    #pragma unroll
    for (int i = 0; i < 8; i++) {
        float v = nrm[i];
        #pragma unroll
        for (int off = 16; off; off >>= 1) v += __shfl_xor_sync(0xffffffffu, v, off);
        if ((tid & 31) == 0) rnorm[lr + i * 8] = v;
    }
    __syncthreads();

    float tau = expf(log_tau[0]);
    float ad  = sigmoidf_(log_blend[0]) * sigmoidf_(logit_decay[0]);

    // Per-row max over 256 cols; lane layout: lane = (ty&1)*16 + tx, so xor<16 mixes tx only.
    #pragma unroll
    for (int i = 0; i < 4; i++) {
        float m = acc[i][0];
        #pragma unroll
        for (int j = 1; j < 16; j++) m = fmaxf(m, acc[i][j]);
        #pragma unroll
        for (int off = 1; off < 16; off <<= 1) m = fmaxf(m, __shfl_xor_sync(0xffffffffu, m, off));
        if (tx == 0) {
            int r = ty + 16 * i;
            float inv = 1.0f / fmaxf(sqrtf(rnorm[r]), EPS_NRM);
            float sim = m * inv;                      // norms > 0: max(acc)/n == max(acc/n)
            float nov = expf(-tau * sim);
            g_scale[row0 + r] = 1.0f - ad + ad * nov;
        }
    }
}

// ---------------------------------------------------------------------------
// 7) GELU pass: out = gelu(x * scale[row]), float4 vectorized
// ---------------------------------------------------------------------------
__global__ void k_gelu(const float4* __restrict__ x4, float4* __restrict__ o4, int n4) {
    int i = blockIdx.x * blockDim.x + threadIdx.x;
    if (i >= n4) return;
    float4 v = x4[i];
    float s = g_scale[i >> 10];   // DD/4 = 1024 float4 per row
    v.x = gelu_tanh(v.x * s);
    v.y = gelu_tanh(v.y * s);
    v.z = gelu_tanh(v.z * s);
    v.w = gelu_tanh(v.w * s);
    o4[i] = v;
}

// ---------------------------------------------------------------------------
extern "C" void kernel_launch(void* const* d_in, const int* in_sizes, int n_in,
                              void* d_out, int out_size) {
    const float* x           = (const float*)d_in[0];
    const float* emas        = (const float*)d_in[1];
    const float* log_tau     = (const float*)d_in[2];
    const float* log_blend   = (const float*)d_in[3];
    const float* logit_decay = (const float*)d_in[4];

    int BT = in_sizes[0] / DD;      // 16384
    int Kp = in_sizes[1] / DD;      // 256
    float* out_x    = (float*)d_out;
    float* out_emas = (float*)d_out + (size_t)in_sizes[0];

    // prototypes
    k_proto_norm<<<Kp, 256>>>(emas);

    // deterministic column sums
    int nrb = BT / 256;             // 64 row blocks
    dim3 gcs(DD / 256, nrb);
    k_colsum_partial<<<gcs, 256>>>(x, 256);
    k_colsum_reduce<<<DD / 256, 256>>>(nrb);

    // argmax side-path + emas output
    k_dots<<<(Kp + 7) / 8, 256>>>(Kp);
    int n4e = in_sizes[1] / 4;
    k_copy4<<<(n4e + 255) / 256, 256>>>((const float4*)emas, (float4*)out_emas, n4e);
    k_update<<<1, 256>>>(emas, logit_decay, out_emas, BT, Kp);

    // main fused GEMM -> per-row scale
    k_sim<<<BT / MT, 256>>>(x, log_tau, log_blend, logit_decay);

    // elementwise gelu
    int n4x = in_sizes[0] / 4;
    k_gelu<<<(n4x + 255) / 256, 256>>>((const float4*)x, (float4*)out_x, n4x);
}

// round 5
// speedup vs baseline: 4.0279x; 4.0117x over previous
#include <cuda_runtime.h>
#include <cuda_bf16.h>
#include <cuda_pipeline_primitives.h>
#include <math.h>
#include <math_constants.h>
#include <cstdint>

// Fixed problem geometry (GELU2_5892695130299): x (4,4096,4096) f32, emas (256,4096) f32.
#define DD       4096
#define KP       256
#define MTILE    64        // rows per CTA (sim kernel)
#define KCH      32        // K chunk (bf16): 64B per row
#define NCH      (DD / KCH)
#define EPS_NRM  1e-12f
#define SQ2PI    0.7978845608028654f

// ---- device scratch (no allocations allowed) ----
__device__ float          g_pnorm[KP * DD];     // normalized prototypes fp32 (k_dots)
__device__ __nv_bfloat16  g_pnorm_bf[KP * DD];  // normalized prototypes bf16 (MMA B)
__device__ float          g_scale[32768];       // per-row output scale
__device__ float          g_partials[128 * DD]; // column-sum partials
__device__ float          g_xsum[DD];
__device__ float          g_dots[KP];

__device__ __forceinline__ float sigmoidf_(float v) { return 1.0f / (1.0f + expf(-v)); }
__device__ __forceinline__ float tanh_fast(float v) {
    float r; asm("tanh.approx.f32 %0, %1;" : "=f"(r) : "f"(v)); return r;
}
__device__ __forceinline__ float gelu_tanh(float y) {
    return 0.5f * y * (1.0f + tanh_fast(SQ2PI * (y + 0.044715f * y * y * y)));
}

__device__ __forceinline__ void mma16816(float* c, uint32_t a0, uint32_t a1,
                                         uint32_t a2, uint32_t a3,
                                         uint32_t b0, uint32_t b1) {
    asm volatile(
        "mma.sync.aligned.m16n8k16.row.col.f32.bf16.bf16.f32 "
        "{%0,%1,%2,%3}, {%4,%5,%6,%7}, {%8,%9}, {%0,%1,%2,%3};"
        : "+f"(c[0]), "+f"(c[1]), "+f"(c[2]), "+f"(c[3])
        : "r"(a0), "r"(a1), "r"(a2), "r"(a3), "r"(b0), "r"(b1));
}

// ---------------------------------------------------------------------------
// 1) Normalize prototypes -> fp32 and bf16 copies
// ---------------------------------------------------------------------------
__global__ void k_proto_norm(const float* __restrict__ emas) {
    __shared__ float red[256];
    int k = blockIdx.x;
    const float* row = emas + (size_t)k * DD;
    float s = 0.f;
    for (int d = threadIdx.x; d < DD; d += 256) { float v = row[d]; s += v * v; }
    red[threadIdx.x] = s; __syncthreads();
    for (int off = 128; off > 0; off >>= 1) {
        if (threadIdx.x < off) red[threadIdx.x] += red[threadIdx.x + off];
        __syncthreads();
    }
    float inv = 1.0f / fmaxf(sqrtf(red[0]), EPS_NRM);
    for (int d = threadIdx.x; d < DD; d += 256) {
        float v = row[d] * inv;
        g_pnorm[(size_t)k * DD + d]    = v;
        g_pnorm_bf[(size_t)k * DD + d] = __float2bfloat16(v);
    }
}

// ---------------------------------------------------------------------------
// 2) Column sums of x (deterministic two-stage)
// ---------------------------------------------------------------------------
__global__ void k_colsum_partial(const float* __restrict__ x, int rows_per) {
    int col = blockIdx.x * 256 + threadIdx.x;
    int rb  = blockIdx.y;
    const float* p = x + (size_t)rb * rows_per * DD + col;
    float s = 0.f;
    #pragma unroll 4
    for (int r = 0; r < rows_per; r++) s += p[(size_t)r * DD];
    g_partials[(size_t)rb * DD + col] = s;
}
__global__ void k_colsum_reduce(int nrb) {
    int col = blockIdx.x * 256 + threadIdx.x;
    float s = 0.f;
    for (int rb = 0; rb < nrb; rb++) s += g_partials[(size_t)rb * DD + col];
    g_xsum[col] = s;
}

// ---------------------------------------------------------------------------
// 3) dots[k] = p_norm[k] . x_sum
// ---------------------------------------------------------------------------
__global__ void k_dots(int Kp) {
    int warp = threadIdx.x >> 5, lane = threadIdx.x & 31;
    int k = blockIdx.x * 8 + warp;
    if (k >= Kp) return;
    const float* pr = g_pnorm + (size_t)k * DD;
    float s = 0.f;
    for (int d = lane; d < DD; d += 32) s += pr[d] * g_xsum[d];
    #pragma unroll
    for (int off = 16; off; off >>= 1) s += __shfl_xor_sync(0xffffffffu, s, off);
    if (lane == 0) g_dots[k] = s;
}

// ---------------------------------------------------------------------------
// 4) Copy emas -> output emas region
// ---------------------------------------------------------------------------
__global__ void k_copy4(const float4* __restrict__ src, float4* __restrict__ dst, int n4) {
    int i = blockIdx.x * blockDim.x + threadIdx.x;
    if (i < n4) dst[i] = src[i];
}

// ---------------------------------------------------------------------------
// 5) argmax(dots) + EMA row update
// ---------------------------------------------------------------------------
__global__ void k_update(const float* __restrict__ emas,
                         const float* __restrict__ logit_decay,
                         float* __restrict__ out_emas, int BT, int Kp) {
    __shared__ float bv[256];
    __shared__ int   bi[256];
    int t = threadIdx.x;
    bv[t] = (t < Kp) ? g_dots[t] : -CUDART_INF_F;
    bi[t] = t;
    __syncthreads();
    for (int off = 128; off > 0; off >>= 1) {
        if (t < off) {
            if (bv[t + off] > bv[t] || (bv[t + off] == bv[t] && bi[t + off] < bi[t])) {
                bv[t] = bv[t + off]; bi[t] = bi[t + off];
            }
        }
        __syncthreads();
    }
    int ks = bi[0];
    float dd = sigmoidf_(logit_decay[0]);
    float invBT = 1.0f / (float)BT;
    for (int d = t; d < DD; d += 256) {
        float mean = g_xsum[d] * invBT;
        out_emas[(size_t)ks * DD + d] = dd * emas[(size_t)ks * DD + d] + (1.0f - dd) * mean;
    }
}

// ---------------------------------------------------------------------------
// 6) HMMA sim-GEMM: 64x256 CTA tile, warp tile 64x32, bf16 mma.sync,
//    cp.async double-buffered B, fp32->bf16 A with row norms folded in.
//    K-major smem rows of 64B with 16B-chunk XOR swizzle (conflict-free).
// ---------------------------------------------------------------------------
__global__ __launch_bounds__(256, 2) void k_sim_mma(const float* __restrict__ x,
                                                    const float* __restrict__ log_tau,
                                                    const float* __restrict__ log_blend,
                                                    const float* __restrict__ logit_decay) {
    __shared__ __align__(16) unsigned char smA[2][MTILE * 64];   //  8 KB
    __shared__ __align__(16) unsigned char smB[2][KP * 64];      // 32 KB

    const int tid  = threadIdx.x;
    const int w    = tid >> 5;
    const int lane = tid & 31;
    const int g    = lane >> 2;      // mma group id (row within 8)
    const int tg   = lane & 3;       // thread-in-group
    const int row0 = blockIdx.x * MTILE;
    const int arow = tid >> 2;       // A loader: row 0..63
    const int apart = tid & 3;       // A loader: 16B chunk 0..3

    const float4* x4 = (const float4*)x;

    float acc[4][4][4];
    #pragma unroll
    for (int mt = 0; mt < 4; mt++)
        #pragma unroll
        for (int nt = 0; nt < 4; nt++)
            #pragma unroll
            for (int q = 0; q < 4; q++) acc[mt][nt][q] = 0.f;

    float nrm = 0.f;

    // ---- helpers (lambdas keep addressing in one place) ----
    auto issueB = [&](int k0, int buf) {
        #pragma unroll
        for (int p = 0; p < 4; p++) {
            int n = (tid >> 2) + p * 64;
            unsigned char* dst = smB[buf] + n * 64 + ((apart ^ ((n >> 1) & 3)) * 16);
            const __nv_bfloat16* src = g_pnorm_bf + (size_t)n * DD + k0 + apart * 8;
            __pipeline_memcpy_async(dst, src, 16);
        }
    };
    auto ldgA = [&](int k0, float4& v0, float4& v1) {
        const float4* p = x4 + (size_t)(row0 + arow) * (DD / 4) + (k0 >> 2) + apart * 2;
        v0 = p[0]; v1 = p[1];
        nrm += v0.x * v0.x + v0.y * v0.y + v0.z * v0.z + v0.w * v0.w
             + v1.x * v1.x + v1.y * v1.y + v1.z * v1.z + v1.w * v1.w;
    };
    auto stsA = [&](int buf, const float4& v0, const float4& v1) {
        __nv_bfloat162 h0 = __floats2bfloat162_rn(v0.x, v0.y);
        __nv_bfloat162 h1 = __floats2bfloat162_rn(v0.z, v0.w);
        __nv_bfloat162 h2 = __floats2bfloat162_rn(v1.x, v1.y);
        __nv_bfloat162 h3 = __floats2bfloat162_rn(v1.z, v1.w);
        uint4* dst = (uint4*)(smA[buf] + arow * 64 + ((apart ^ ((arow >> 1) & 3)) * 16));
        *dst = make_uint4(*(uint32_t*)&h0, *(uint32_t*)&h1, *(uint32_t*)&h2, *(uint32_t*)&h3);
    };
    auto compute = [&](int buf) {
        const unsigned char* Ab = smA[buf];
        const unsigned char* Bb = smB[buf];
        #pragma unroll
        for (int ks = 0; ks < 2; ks++) {
            uint32_t b0[4], b1[4];
            #pragma unroll
            for (int nt = 0; nt < 4; nt++) {
                int n = w * 32 + nt * 8 + g;
                int s = (n >> 1) & 3;
                const unsigned char* base = Bb + n * 64;
                b0[nt] = *(const uint32_t*)(base + (((2 * ks)     ^ s) * 16) + 4 * tg);
                b1[nt] = *(const uint32_t*)(base + (((2 * ks + 1) ^ s) * 16) + 4 * tg);
            }
            #pragma unroll
            for (int mt = 0; mt < 4; mt++) {
                int r0r = mt * 16 + g, r1r = r0r + 8;
                int s0 = (r0r >> 1) & 3, s1 = (r1r >> 1) & 3;
                uint32_t a0 = *(const uint32_t*)(Ab + r0r * 64 + (((2 * ks)     ^ s0) * 16) + 4 * tg);
                uint32_t a1 = *(const uint32_t*)(Ab + r1r * 64 + (((2 * ks)     ^ s1) * 16) + 4 * tg);
                uint32_t a2 = *(const uint32_t*)(Ab + r0r * 64 + (((2 * ks + 1) ^ s0) * 16) + 4 * tg);
                uint32_t a3 = *(const uint32_t*)(Ab + r1r * 64 + (((2 * ks + 1) ^ s1) * 16) + 4 * tg);
                #pragma unroll
                for (int nt = 0; nt < 4; nt++)
                    mma16816(acc[mt][nt], a0, a1, a2, a3, b0[nt], b1[nt]);
            }
        }
    };

    // ---- prologue: stage chunk 0 ----
    issueB(0, 0);
    __pipeline_commit();
    {
        float4 v0, v1;
        ldgA(0, v0, v1);
        stsA(0, v0, v1);
    }
    __pipeline_wait_prior(0);
    __syncthreads();

    // ---- main loop ----
    for (int ic = 0; ic < NCH; ic++) {
        int buf = ic & 1, nbuf = buf ^ 1;
        float4 nv0, nv1;
        if (ic < NCH - 1) {
            issueB((ic + 1) * KCH, nbuf);
            __pipeline_commit();
            ldgA((ic + 1) * KCH, nv0, nv1);
        }
        compute(buf);
        if (ic < NCH - 1) {
            stsA(nbuf, nv0, nv1);
            __pipeline_wait_prior(0);
        }
        __syncthreads();
    }

    // ---- epilogue (alias scratch onto smA) ----
    float* rowmax = (float*)smA;                         // 64*8 floats
    float* rn     = (float*)((unsigned char*)smA + 2048); // 64 floats

    // row sumsq: 4 loader threads per row share a warp -> shfl reduce
    nrm += __shfl_xor_sync(0xffffffffu, nrm, 1);
    nrm += __shfl_xor_sync(0xffffffffu, nrm, 2);
    if ((tid & 3) == 0) rn[arow] = nrm;

    #pragma unroll
    for (int mt = 0; mt < 4; mt++) {
        float m0 = -CUDART_INF_F, m1 = -CUDART_INF_F;
        #pragma unroll
        for (int nt = 0; nt < 4; nt++) {
            m0 = fmaxf(m0, fmaxf(acc[mt][nt][0], acc[mt][nt][1]));
            m1 = fmaxf(m1, fmaxf(acc[mt][nt][2], acc[mt][nt][3]));
        }
        m0 = fmaxf(m0, __shfl_xor_sync(0xffffffffu, m0, 1));
        m0 = fmaxf(m0, __shfl_xor_sync(0xffffffffu, m0, 2));
        m1 = fmaxf(m1, __shfl_xor_sync(0xffffffffu, m1, 1));
        m1 = fmaxf(m1, __shfl_xor_sync(0xffffffffu, m1, 2));
        if (tg == 0) {
            rowmax[(mt * 16 + g) * 8 + w]     = m0;
            rowmax[(mt * 16 + 8 + g) * 8 + w] = m1;
        }
    }
    __syncthreads();

    if (tid < MTILE) {
        float m = rowmax[tid * 8];
        #pragma unroll
        for (int j = 1; j < 8; j++) m = fmaxf(m, rowmax[tid * 8 + j]);
        float inv = 1.0f / fmaxf(sqrtf(rn[tid]), EPS_NRM);
        float tau = expf(log_tau[0]);
        float ad_ = sigmoidf_(log_blend[0]) * sigmoidf_(logit_decay[0]);
        g_scale[row0 + tid] = 1.0f - ad_ + ad_ * expf(-tau * (m * inv));
    }
}

// ---------------------------------------------------------------------------
// 7) GELU pass (memory-bound; HW tanh.approx)
// ---------------------------------------------------------------------------
__global__ void k_gelu(const float4* __restrict__ x4, float4* __restrict__ o4, int n4) {
    int i = blockIdx.x * blockDim.x + threadIdx.x;
    if (i >= n4) return;
    float4 v = x4[i];
    float s = g_scale[i >> 10];
    v.x = gelu_tanh(v.x * s);
    v.y = gelu_tanh(v.y * s);
    v.z = gelu_tanh(v.z * s);
    v.w = gelu_tanh(v.w * s);
    o4[i] = v;
}

// ---------------------------------------------------------------------------
extern "C" void kernel_launch(void* const* d_in, const int* in_sizes, int n_in,
                              void* d_out, int out_size) {
    const float* x           = (const float*)d_in[0];
    const float* emas        = (const float*)d_in[1];
    const float* log_tau     = (const float*)d_in[2];
    const float* log_blend   = (const float*)d_in[3];
    const float* logit_decay = (const float*)d_in[4];

    int BT = in_sizes[0] / DD;   // 16384
    int Kp = in_sizes[1] / DD;   // 256
    float* out_x    = (float*)d_out;
    float* out_emas = (float*)d_out + (size_t)in_sizes[0];

    k_proto_norm<<<Kp, 256>>>(emas);

    int nrb = BT / 256;
    dim3 gcs(DD / 256, nrb);
    k_colsum_partial<<<gcs, 256>>>(x, 256);
    k_colsum_reduce<<<DD / 256, 256>>>(nrb);

    k_dots<<<(Kp + 7) / 8, 256>>>(Kp);
    int n4e = in_sizes[1] / 4;
    k_copy4<<<(n4e + 255) / 256, 256>>>((const float4*)emas, (float4*)out_emas, n4e);
    k_update<<<1, 256>>>(emas, logit_decay, out_emas, BT, Kp);

    k_sim_mma<<<BT / MTILE, 256>>>(x, log_tau, log_blend, logit_decay);

    int n4x = in_sizes[0] / 4;
    k_gelu<<<(n4x + 255) / 256, 256>>>((const float4*)x, (float4*)out_x, n4x);
}

// round 6
// speedup vs baseline: 4.6528x; 1.1551x over previous
#include <cuda_runtime.h>
#include <cuda_bf16.h>
#include <cuda_pipeline_primitives.h>
#include <math.h>
#include <math_constants.h>
#include <cstdint>

// Fixed problem geometry (GELU2_5892695130299): x (4,4096,4096) f32, emas (256,4096) f32.
#define DD       4096
#define KP       256
#define MTILE    64        // rows per CTA (sim kernel)
#define KCH      32        // K chunk (bf16): 64B per row
#define NCH      (DD / KCH)
#define NCTA     256       // BT / MTILE
#define EPS_NRM  1e-12f
#define SQ2PI    0.7978845608028654f

// ---- device scratch (no allocations allowed) ----
__device__ float          g_pnorm[KP * DD];      // normalized prototypes fp32 (k_dots)
__device__ __nv_bfloat16  g_pnorm_bf[KP * DD];   // normalized prototypes bf16 (MMA B)
__device__ float          g_partials[NCTA * DD]; // per-CTA column-sum partials (4 MB)
__device__ float          g_xsum[DD];
__device__ float          g_dots[KP];

__device__ __forceinline__ float sigmoidf_(float v) { return 1.0f / (1.0f + expf(-v)); }
__device__ __forceinline__ float tanh_fast(float v) {
    float r; asm("tanh.approx.f32 %0, %1;" : "=f"(r) : "f"(v)); return r;
}
__device__ __forceinline__ float gelu_tanh(float y) {
    return 0.5f * y * (1.0f + tanh_fast(SQ2PI * (y + 0.044715f * y * y * y)));
}

__device__ __forceinline__ void mma16816(float* c, uint32_t a0, uint32_t a1,
                                         uint32_t a2, uint32_t a3,
                                         uint32_t b0, uint32_t b1) {
    asm volatile(
        "mma.sync.aligned.m16n8k16.row.col.f32.bf16.bf16.f32 "
        "{%0,%1,%2,%3}, {%4,%5,%6,%7}, {%8,%9}, {%0,%1,%2,%3};"
        : "+f"(c[0]), "+f"(c[1]), "+f"(c[2]), "+f"(c[3])
        : "r"(a0), "r"(a1), "r"(a2), "r"(a3), "r"(b0), "r"(b1));
}

// ---------------------------------------------------------------------------
// 1) Normalize prototypes -> fp32 and bf16 copies
// ---------------------------------------------------------------------------
__global__ void k_proto_norm(const float* __restrict__ emas) {
    __shared__ float red[256];
    int k = blockIdx.x;
    const float* row = emas + (size_t)k * DD;
    float s = 0.f;
    for (int d = threadIdx.x; d < DD; d += 256) { float v = row[d]; s += v * v; }
    red[threadIdx.x] = s; __syncthreads();
    for (int off = 128; off > 0; off >>= 1) {
        if (threadIdx.x < off) red[threadIdx.x] += red[threadIdx.x + off];
        __syncthreads();
    }
    float inv = 1.0f / fmaxf(sqrtf(red[0]), EPS_NRM);
    for (int d = threadIdx.x; d < DD; d += 256) {
        float v = row[d] * inv;
        g_pnorm[(size_t)k * DD + d]    = v;
        g_pnorm_bf[(size_t)k * DD + d] = __float2bfloat16(v);
    }
}

// ---------------------------------------------------------------------------
// 2) Fused kernel: HMMA sim-GEMM (64x256 tile) -> per-row scale -> GELU pass
//    over the same 64 rows, with per-CTA column sums folded into the GELU
//    loads (each thread exclusively owns columns c == tid (mod 256)).
// ---------------------------------------------------------------------------
__global__ __launch_bounds__(256, 2) void k_sim_fused(const float* __restrict__ x,
                                                      float* __restrict__ out_x,
                                                      const float* __restrict__ log_tau,
                                                      const float* __restrict__ log_blend,
                                                      const float* __restrict__ logit_decay) {
    __shared__ __align__(16) unsigned char smA[2][MTILE * 64];   //  8 KB
    __shared__ __align__(16) unsigned char smB[2][KP * 64];      // 32 KB

    const int tid  = threadIdx.x;
    const int w    = tid >> 5;
    const int lane = tid & 31;
    const int g    = lane >> 2;
    const int tg   = lane & 3;
    const int row0 = blockIdx.x * MTILE;
    const int arow = tid >> 2;
    const int apart = tid & 3;

    const float4* x4 = (const float4*)x;

    float acc[4][4][4];
    #pragma unroll
    for (int mt = 0; mt < 4; mt++)
        #pragma unroll
        for (int nt = 0; nt < 4; nt++)
            #pragma unroll
            for (int q = 0; q < 4; q++) acc[mt][nt][q] = 0.f;

    float nrm = 0.f;

    auto issueB = [&](int k0, int buf) {
        #pragma unroll
        for (int p = 0; p < 4; p++) {
            int n = (tid >> 2) + p * 64;
            unsigned char* dst = smB[buf] + n * 64 + ((apart ^ ((n >> 1) & 3)) * 16);
            const __nv_bfloat16* src = g_pnorm_bf + (size_t)n * DD + k0 + apart * 8;
            __pipeline_memcpy_async(dst, src, 16);
        }
    };
    auto ldgA = [&](int k0, float4& v0, float4& v1) {
        const float4* p = x4 + (size_t)(row0 + arow) * (DD / 4) + (k0 >> 2) + apart * 2;
        v0 = p[0]; v1 = p[1];
        nrm += v0.x * v0.x + v0.y * v0.y + v0.z * v0.z + v0.w * v0.w
             + v1.x * v1.x + v1.y * v1.y + v1.z * v1.z + v1.w * v1.w;
    };
    auto stsA = [&](int buf, const float4& v0, const float4& v1) {
        __nv_bfloat162 h0 = __floats2bfloat162_rn(v0.x, v0.y);
        __nv_bfloat162 h1 = __floats2bfloat162_rn(v0.z, v0.w);
        __nv_bfloat162 h2 = __floats2bfloat162_rn(v1.x, v1.y);
        __nv_bfloat162 h3 = __floats2bfloat162_rn(v1.z, v1.w);
        uint4* dst = (uint4*)(smA[buf] + arow * 64 + ((apart ^ ((arow >> 1) & 3)) * 16));
        *dst = make_uint4(*(uint32_t*)&h0, *(uint32_t*)&h1, *(uint32_t*)&h2, *(uint32_t*)&h3);
    };
    auto compute = [&](int buf) {
        const unsigned char* Ab = smA[buf];
        const unsigned char* Bb = smB[buf];
        #pragma unroll
        for (int ks = 0; ks < 2; ks++) {
            uint32_t b0[4], b1[4];
            #pragma unroll
            for (int nt = 0; nt < 4; nt++) {
                int n = w * 32 + nt * 8 + g;
                int s = (n >> 1) & 3;
                const unsigned char* base = Bb + n * 64;
                b0[nt] = *(const uint32_t*)(base + (((2 * ks)     ^ s) * 16) + 4 * tg);
                b1[nt] = *(const uint32_t*)(base + (((2 * ks + 1) ^ s) * 16) + 4 * tg);
            }
            #pragma unroll
            for (int mt = 0; mt < 4; mt++) {
                int r0r = mt * 16 + g, r1r = r0r + 8;
                int s0 = (r0r >> 1) & 3, s1 = (r1r >> 1) & 3;
                uint32_t a0 = *(const uint32_t*)(Ab + r0r * 64 + (((2 * ks)     ^ s0) * 16) + 4 * tg);
                uint32_t a1 = *(const uint32_t*)(Ab + r1r * 64 + (((2 * ks)     ^ s1) * 16) + 4 * tg);
                uint32_t a2 = *(const uint32_t*)(Ab + r0r * 64 + (((2 * ks + 1) ^ s0) * 16) + 4 * tg);
                uint32_t a3 = *(const uint32_t*)(Ab + r1r * 64 + (((2 * ks + 1) ^ s1) * 16) + 4 * tg);
                #pragma unroll
                for (int nt = 0; nt < 4; nt++)
                    mma16816(acc[mt][nt], a0, a1, a2, a3, b0[nt], b1[nt]);
            }
        }
    };

    // ---- prologue ----
    issueB(0, 0);
    __pipeline_commit();
    {
        float4 v0, v1;
        ldgA(0, v0, v1);
        stsA(0, v0, v1);
    }
    __pipeline_wait_prior(0);
    __syncthreads();

    // ---- main GEMM loop ----
    for (int ic = 0; ic < NCH; ic++) {
        int buf = ic & 1, nbuf = buf ^ 1;
        float4 nv0, nv1;
        if (ic < NCH - 1) {
            issueB((ic + 1) * KCH, nbuf);
            __pipeline_commit();
            ldgA((ic + 1) * KCH, nv0, nv1);
        }
        compute(buf);
        if (ic < NCH - 1) {
            stsA(nbuf, nv0, nv1);
            __pipeline_wait_prior(0);
        }
        __syncthreads();
    }

    // ---- epilogue: row max + row norm -> scale (smem scratch aliases smA) ----
    float* rowmax = (float*)smA;                          // 64*8 floats
    float* sc     = (float*)((unsigned char*)smA + 2048); // 64 floats (norms, then scale)

    nrm += __shfl_xor_sync(0xffffffffu, nrm, 1);
    nrm += __shfl_xor_sync(0xffffffffu, nrm, 2);
    if ((tid & 3) == 0) sc[arow] = nrm;

    #pragma unroll
    for (int mt = 0; mt < 4; mt++) {
        float m0 = -CUDART_INF_F, m1 = -CUDART_INF_F;
        #pragma unroll
        for (int nt = 0; nt < 4; nt++) {
            m0 = fmaxf(m0, fmaxf(acc[mt][nt][0], acc[mt][nt][1]));
            m1 = fmaxf(m1, fmaxf(acc[mt][nt][2], acc[mt][nt][3]));
        }
        m0 = fmaxf(m0, __shfl_xor_sync(0xffffffffu, m0, 1));
        m0 = fmaxf(m0, __shfl_xor_sync(0xffffffffu, m0, 2));
        m1 = fmaxf(m1, __shfl_xor_sync(0xffffffffu, m1, 1));
        m1 = fmaxf(m1, __shfl_xor_sync(0xffffffffu, m1, 2));
        if (tg == 0) {
            rowmax[(mt * 16 + g) * 8 + w]     = m0;
            rowmax[(mt * 16 + 8 + g) * 8 + w] = m1;
        }
    }
    __syncthreads();

    if (tid < MTILE) {
        float m = rowmax[tid * 8];
        #pragma unroll
        for (int j = 1; j < 8; j++) m = fmaxf(m, rowmax[tid * 8 + j]);
        float inv = 1.0f / fmaxf(sqrtf(sc[tid]), EPS_NRM);
        float tau = expf(log_tau[0]);
        float ad_ = sigmoidf_(log_blend[0]) * sigmoidf_(logit_decay[0]);
        sc[tid] = 1.0f - ad_ + ad_ * expf(-tau * (m * inv));
    }
    __syncthreads();

    // ---- fused GELU + per-CTA column partial sums over this 64-row block ----
    // idx = tid + 256*j : thread exclusively owns float4 columns tid+256*(j&3).
    float cs[16];
    #pragma unroll
    for (int p = 0; p < 16; p++) cs[p] = 0.f;

    const float4* xr = x4 + (size_t)row0 * (DD / 4);
    float4* orow = (float4*)out_x + (size_t)row0 * (DD / 4);

    #pragma unroll 4
    for (int j = 0; j < 256; j++) {
        int idx = tid + j * 256;
        float4 v = xr[idx];
        int slot = (j & 3) * 4;
        cs[slot + 0] += v.x; cs[slot + 1] += v.y;
        cs[slot + 2] += v.z; cs[slot + 3] += v.w;
        float s = sc[idx >> 10];
        v.x = gelu_tanh(v.x * s);
        v.y = gelu_tanh(v.y * s);
        v.z = gelu_tanh(v.z * s);
        v.w = gelu_tanh(v.w * s);
        orow[idx] = v;
    }

    float4* gp = (float4*)(g_partials + (size_t)blockIdx.x * DD);
    #pragma unroll
    for (int slot = 0; slot < 4; slot++)
        gp[tid + 256 * slot] = make_float4(cs[slot * 4 + 0], cs[slot * 4 + 1],
                                           cs[slot * 4 + 2], cs[slot * 4 + 3]);
}

// ---------------------------------------------------------------------------
// 3) Reduce per-CTA column partials -> g_xsum (deterministic order)
// ---------------------------------------------------------------------------
__global__ void k_colsum_reduce() {
    int col = blockIdx.x * 256 + threadIdx.x;
    float s = 0.f;
    for (int rb = 0; rb < NCTA; rb++) s += g_partials[(size_t)rb * DD + col];
    g_xsum[col] = s;
}

// ---------------------------------------------------------------------------
// 4) dots[k] = p_norm[k] . x_sum  (float4, one warp per k)
// ---------------------------------------------------------------------------
__global__ void k_dots(int Kp) {
    int warp = threadIdx.x >> 5, lane = threadIdx.x & 31;
    int k = blockIdx.x * 4 + warp;
    if (k >= Kp) return;
    const float4* pr = (const float4*)(g_pnorm + (size_t)k * DD);
    const float4* xs = (const float4*)g_xsum;
    float s = 0.f;
    #pragma unroll 4
    for (int d = lane; d < DD / 4; d += 32) {
        float4 a = pr[d], b = xs[d];
        s += a.x * b.x + a.y * b.y + a.z * b.z + a.w * b.w;
    }
    #pragma unroll
    for (int off = 16; off; off >>= 1) s += __shfl_xor_sync(0xffffffffu, s, off);
    if (lane == 0) g_dots[k] = s;
}

// ---------------------------------------------------------------------------
// 5) Copy emas -> output emas region
// ---------------------------------------------------------------------------
__global__ void k_copy4(const float4* __restrict__ src, float4* __restrict__ dst, int n4) {
    int i = blockIdx.x * blockDim.x + threadIdx.x;
    if (i < n4) dst[i] = src[i];
}

// ---------------------------------------------------------------------------
// 6) argmax(dots) + EMA row update
// ---------------------------------------------------------------------------
__global__ void k_update(const float* __restrict__ emas,
                         const float* __restrict__ logit_decay,
                         float* __restrict__ out_emas, int BT, int Kp) {
    __shared__ float bv[256];
    __shared__ int   bi[256];
    int t = threadIdx.x;
    bv[t] = (t < Kp) ? g_dots[t] : -CUDART_INF_F;
    bi[t] = t;
    __syncthreads();
    for (int off = 128; off > 0; off >>= 1) {
        if (t < off) {
            if (bv[t + off] > bv[t] || (bv[t + off] == bv[t] && bi[t + off] < bi[t])) {
                bv[t] = bv[t + off]; bi[t] = bi[t + off];
            }
        }
        __syncthreads();
    }
    int ks = bi[0];
    float dd = sigmoidf_(logit_decay[0]);
    float invBT = 1.0f / (float)BT;
    for (int d = t; d < DD; d += 256) {
        float mean = g_xsum[d] * invBT;
        out_emas[(size_t)ks * DD + d] = dd * emas[(size_t)ks * DD + d] + (1.0f - dd) * mean;
    }
}

// ---------------------------------------------------------------------------
extern "C" void kernel_launch(void* const* d_in, const int* in_sizes, int n_in,
                              void* d_out, int out_size) {
    const float* x           = (const float*)d_in[0];
    const float* emas        = (const float*)d_in[1];
    const float* log_tau     = (const float*)d_in[2];
    const float* log_blend   = (const float*)d_in[3];
    const float* logit_decay = (const float*)d_in[4];

    int BT = in_sizes[0] / DD;   // 16384
    int Kp = in_sizes[1] / DD;   // 256
    float* out_x    = (float*)d_out;
    float* out_emas = (float*)d_out + (size_t)in_sizes[0];

    k_proto_norm<<<Kp, 256>>>(emas);

    // big fused pass: sim GEMM + scale + gelu + column partials
    k_sim_fused<<<BT / MTILE, 256>>>(x, out_x, log_tau, log_blend, logit_decay);

    // tail: column sums -> dots -> argmax EMA update
    k_colsum_reduce<<<DD / 256, 256>>>();
    k_dots<<<(Kp + 3) / 4, 128>>>(Kp);
    int n4e = in_sizes[1] / 4;
    k_copy4<<<(n4e + 255) / 256, 256>>>((const float4*)emas, (float4*)out_emas, n4e);
    k_update<<<1, 256>>>(emas, logit_decay, out_emas, BT, Kp);
}

// round 7
// speedup vs baseline: 4.6737x; 1.0045x over previous
#include <cuda_runtime.h>
#include <cuda_bf16.h>
#include <cuda_pipeline_primitives.h>
#include <math.h>
#include <math_constants.h>
#include <cstdint>

// Fixed problem geometry (GELU2_5892695130299): x (4,4096,4096) f32, emas (256,4096) f32.
#define DD       4096
#define KP       256
#define MTILE    64        // rows per CTA (sim kernel)
#define KCH      32        // K chunk (bf16): 64B per row
#define NCH      (DD / KCH)
#define NCTA     256       // BT / MTILE
#define EPS_NRM  1e-12f
#define SQ2PI    0.7978845608028654f

// ---- device scratch (no allocations allowed) ----
__device__ float          g_pnorm[KP * DD];      // normalized prototypes fp32 (k_dots)
__device__ __nv_bfloat16  g_pnorm_bf[KP * DD];   // normalized prototypes bf16 (MMA B)
__device__ float          g_partials[NCTA * DD]; // per-CTA column-sum partials (4 MB)
__device__ float          g_xsum[DD];
__device__ float          g_dots[KP];

__device__ __forceinline__ float sigmoidf_(float v) { return 1.0f / (1.0f + expf(-v)); }
__device__ __forceinline__ float tanh_fast(float v) {
    float r; asm("tanh.approx.f32 %0, %1;" : "=f"(r) : "f"(v)); return r;
}
__device__ __forceinline__ float gelu_tanh(float y) {
    return 0.5f * y * (1.0f + tanh_fast(SQ2PI * (y + 0.044715f * y * y * y)));
}

__device__ __forceinline__ void mma16816(float* c, uint32_t a0, uint32_t a1,
                                         uint32_t a2, uint32_t a3,
                                         uint32_t b0, uint32_t b1) {
    asm volatile(
        "mma.sync.aligned.m16n8k16.row.col.f32.bf16.bf16.f32 "
        "{%0,%1,%2,%3}, {%4,%5,%6,%7}, {%8,%9}, {%0,%1,%2,%3};"
        : "+f"(c[0]), "+f"(c[1]), "+f"(c[2]), "+f"(c[3])
        : "r"(a0), "r"(a1), "r"(a2), "r"(a3), "r"(b0), "r"(b1));
}

// ---------------------------------------------------------------------------
// 1) Normalize prototypes -> fp32 and bf16 copies
// ---------------------------------------------------------------------------
__global__ void k_proto_norm(const float* __restrict__ emas) {
    __shared__ float red[256];
    int k = blockIdx.x;
    const float* row = emas + (size_t)k * DD;
    float s = 0.f;
    for (int d = threadIdx.x; d < DD; d += 256) { float v = row[d]; s += v * v; }
    red[threadIdx.x] = s; __syncthreads();
    for (int off = 128; off > 0; off >>= 1) {
        if (threadIdx.x < off) red[threadIdx.x] += red[threadIdx.x + off];
        __syncthreads();
    }
    float inv = 1.0f / fmaxf(sqrtf(red[0]), EPS_NRM);
    for (int d = threadIdx.x; d < DD; d += 256) {
        float v = row[d] * inv;
        g_pnorm[(size_t)k * DD + d]    = v;
        g_pnorm_bf[(size_t)k * DD + d] = __float2bfloat16(v);
    }
}

// ---------------------------------------------------------------------------
// 2) Fused kernel: HMMA sim-GEMM (64x256 tile) -> per-row scale -> GELU pass
//    over the same 64 rows, with per-CTA column sums folded into the GELU
//    loads (each thread exclusively owns columns c == tid (mod 256)).
// ---------------------------------------------------------------------------
__global__ __launch_bounds__(256, 2) void k_sim_fused(const float* __restrict__ x,
                                                      float* __restrict__ out_x,
                                                      const float* __restrict__ log_tau,
                                                      const float* __restrict__ log_blend,
                                                      const float* __restrict__ logit_decay) {
    __shared__ __align__(16) unsigned char smA[2][MTILE * 64];   //  8 KB
    __shared__ __align__(16) unsigned char smB[2][KP * 64];      // 32 KB

    const int tid  = threadIdx.x;
    const int w    = tid >> 5;
    const int lane = tid & 31;
    const int g    = lane >> 2;
    const int tg   = lane & 3;
    const int row0 = blockIdx.x * MTILE;
    const int arow = tid >> 2;
    const int apart = tid & 3;

    const float4* x4 = (const float4*)x;

    float acc[4][4][4];
    #pragma unroll
    for (int mt = 0; mt < 4; mt++)
        #pragma unroll
        for (int nt = 0; nt < 4; nt++)
            #pragma unroll
            for (int q = 0; q < 4; q++) acc[mt][nt][q] = 0.f;

    float nrm = 0.f;

    auto issueB = [&](int k0, int buf) {
        #pragma unroll
        for (int p = 0; p < 4; p++) {
            int n = (tid >> 2) + p * 64;
            unsigned char* dst = smB[buf] + n * 64 + ((apart ^ ((n >> 1) & 3)) * 16);
            const __nv_bfloat16* src = g_pnorm_bf + (size_t)n * DD + k0 + apart * 8;
            __pipeline_memcpy_async(dst, src, 16);
        }
    };
    auto ldgA = [&](int k0, float4& v0, float4& v1) {
        const float4* p = x4 + (size_t)(row0 + arow) * (DD / 4) + (k0 >> 2) + apart * 2;
        v0 = p[0]; v1 = p[1];
        nrm += v0.x * v0.x + v0.y * v0.y + v0.z * v0.z + v0.w * v0.w
             + v1.x * v1.x + v1.y * v1.y + v1.z * v1.z + v1.w * v1.w;
    };
    auto stsA = [&](int buf, const float4& v0, const float4& v1) {
        __nv_bfloat162 h0 = __floats2bfloat162_rn(v0.x, v0.y);
        __nv_bfloat162 h1 = __floats2bfloat162_rn(v0.z, v0.w);
        __nv_bfloat162 h2 = __floats2bfloat162_rn(v1.x, v1.y);
        __nv_bfloat162 h3 = __floats2bfloat162_rn(v1.z, v1.w);
        uint4* dst = (uint4*)(smA[buf] + arow * 64 + ((apart ^ ((arow >> 1) & 3)) * 16));
        *dst = make_uint4(*(uint32_t*)&h0, *(uint32_t*)&h1, *(uint32_t*)&h2, *(uint32_t*)&h3);
    };
    auto compute = [&](int buf) {
        const unsigned char* Ab = smA[buf];
        const unsigned char* Bb = smB[buf];
        #pragma unroll
        for (int ks = 0; ks < 2; ks++) {
            uint32_t b0[4], b1[4];
            #pragma unroll
            for (int nt = 0; nt < 4; nt++) {
                int n = w * 32 + nt * 8 + g;
                int s = (n >> 1) & 3;
                const unsigned char* base = Bb + n * 64;
                b0[nt] = *(const uint32_t*)(base + (((2 * ks)     ^ s) * 16) + 4 * tg);
                b1[nt] = *(const uint32_t*)(base + (((2 * ks + 1) ^ s) * 16) + 4 * tg);
            }
            #pragma unroll
            for (int mt = 0; mt < 4; mt++) {
                int r0r = mt * 16 + g, r1r = r0r + 8;
                int s0 = (r0r >> 1) & 3, s1 = (r1r >> 1) & 3;
                uint32_t a0 = *(const uint32_t*)(Ab + r0r * 64 + (((2 * ks)     ^ s0) * 16) + 4 * tg);
                uint32_t a1 = *(const uint32_t*)(Ab + r1r * 64 + (((2 * ks)     ^ s1) * 16) + 4 * tg);
                uint32_t a2 = *(const uint32_t*)(Ab + r0r * 64 + (((2 * ks + 1) ^ s0) * 16) + 4 * tg);
                uint32_t a3 = *(const uint32_t*)(Ab + r1r * 64 + (((2 * ks + 1) ^ s1) * 16) + 4 * tg);
                #pragma unroll
                for (int nt = 0; nt < 4; nt++)
                    mma16816(acc[mt][nt], a0, a1, a2, a3, b0[nt], b1[nt]);
            }
        }
    };

    // ---- prologue ----
    issueB(0, 0);
    __pipeline_commit();
    {
        float4 v0, v1;
        ldgA(0, v0, v1);
        stsA(0, v0, v1);
    }
    __pipeline_wait_prior(0);
    __syncthreads();

    // ---- main GEMM loop ----
    for (int ic = 0; ic < NCH; ic++) {
        int buf = ic & 1, nbuf = buf ^ 1;
        float4 nv0, nv1;
        if (ic < NCH - 1) {
            issueB((ic + 1) * KCH, nbuf);
            __pipeline_commit();
            ldgA((ic + 1) * KCH, nv0, nv1);
        }
        compute(buf);
        if (ic < NCH - 1) {
            stsA(nbuf, nv0, nv1);
            __pipeline_wait_prior(0);
        }
        __syncthreads();
    }

    // ---- epilogue: row max + row norm -> scale (smem scratch aliases smA) ----
    float* rowmax = (float*)smA;                          // 64*8 floats
    float* sc     = (float*)((unsigned char*)smA + 2048); // 64 floats (norms, then scale)

    nrm += __shfl_xor_sync(0xffffffffu, nrm, 1);
    nrm += __shfl_xor_sync(0xffffffffu, nrm, 2);
    if ((tid & 3) == 0) sc[arow] = nrm;

    #pragma unroll
    for (int mt = 0; mt < 4; mt++) {
        float m0 = -CUDART_INF_F, m1 = -CUDART_INF_F;
        #pragma unroll
        for (int nt = 0; nt < 4; nt++) {
            m0 = fmaxf(m0, fmaxf(acc[mt][nt][0], acc[mt][nt][1]));
            m1 = fmaxf(m1, fmaxf(acc[mt][nt][2], acc[mt][nt][3]));
        }
        m0 = fmaxf(m0, __shfl_xor_sync(0xffffffffu, m0, 1));
        m0 = fmaxf(m0, __shfl_xor_sync(0xffffffffu, m0, 2));
        m1 = fmaxf(m1, __shfl_xor_sync(0xffffffffu, m1, 1));
        m1 = fmaxf(m1, __shfl_xor_sync(0xffffffffu, m1, 2));
        if (tg == 0) {
            rowmax[(mt * 16 + g) * 8 + w]     = m0;
            rowmax[(mt * 16 + 8 + g) * 8 + w] = m1;
        }
    }
    __syncthreads();

    if (tid < MTILE) {
        float m = rowmax[tid * 8];
        #pragma unroll
        for (int j = 1; j < 8; j++) m = fmaxf(m, rowmax[tid * 8 + j]);
        float inv = 1.0f / fmaxf(sqrtf(sc[tid]), EPS_NRM);
        float tau = expf(log_tau[0]);
        float ad_ = sigmoidf_(log_blend[0]) * sigmoidf_(logit_decay[0]);
        sc[tid] = 1.0f - ad_ + ad_ * expf(-tau * (m * inv));
    }
    __syncthreads();

    // ---- fused GELU + per-CTA column partial sums over this 64-row block ----
    // idx = tid + 256*j : thread exclusively owns float4 columns tid+256*(j&3).
    float cs[16];
    #pragma unroll
    for (int p = 0; p < 16; p++) cs[p] = 0.f;

    const float4* xr = x4 + (size_t)row0 * (DD / 4);
    float4* orow = (float4*)out_x + (size_t)row0 * (DD / 4);

    #pragma unroll 4
    for (int j = 0; j < 256; j++) {
        int idx = tid + j * 256;
        float4 v = xr[idx];
        int slot = (j & 3) * 4;
        cs[slot + 0] += v.x; cs[slot + 1] += v.y;
        cs[slot + 2] += v.z; cs[slot + 3] += v.w;
        float s = sc[idx >> 10];
        v.x = gelu_tanh(v.x * s);
        v.y = gelu_tanh(v.y * s);
        v.z = gelu_tanh(v.z * s);
        v.w = gelu_tanh(v.w * s);
        orow[idx] = v;
    }

    float4* gp = (float4*)(g_partials + (size_t)blockIdx.x * DD);
    #pragma unroll
    for (int slot = 0; slot < 4; slot++)
        gp[tid + 256 * slot] = make_float4(cs[slot * 4 + 0], cs[slot * 4 + 1],
                                           cs[slot * 4 + 2], cs[slot * 4 + 3]);
}

// ---------------------------------------------------------------------------
// 3) Reduce per-CTA column partials -> g_xsum (deterministic order)
// ---------------------------------------------------------------------------
__global__ void k_colsum_reduce() {
    int col = blockIdx.x * 256 + threadIdx.x;
    float s = 0.f;
    for (int rb = 0; rb < NCTA; rb++) s += g_partials[(size_t)rb * DD + col];
    g_xsum[col] = s;
}

// ---------------------------------------------------------------------------
// 4) dots[k] = p_norm[k] . x_sum  (float4, one warp per k)
// ---------------------------------------------------------------------------
__global__ void k_dots(int Kp) {
    int warp = threadIdx.x >> 5, lane = threadIdx.x & 31;
    int k = blockIdx.x * 4 + warp;
    if (k >= Kp) return;
    const float4* pr = (const float4*)(g_pnorm + (size_t)k * DD);
    const float4* xs = (const float4*)g_xsum;
    float s = 0.f;
    #pragma unroll 4
    for (int d = lane; d < DD / 4; d += 32) {
        float4 a = pr[d], b = xs[d];
        s += a.x * b.x + a.y * b.y + a.z * b.z + a.w * b.w;
    }
    #pragma unroll
    for (int off = 16; off; off >>= 1) s += __shfl_xor_sync(0xffffffffu, s, off);
    if (lane == 0) g_dots[k] = s;
}

// ---------------------------------------------------------------------------
// 5) Copy emas -> output emas region
// ---------------------------------------------------------------------------
__global__ void k_copy4(const float4* __restrict__ src, float4* __restrict__ dst, int n4) {
    int i = blockIdx.x * blockDim.x + threadIdx.x;
    if (i < n4) dst[i] = src[i];
}

// ---------------------------------------------------------------------------
// 6) argmax(dots) + EMA row update
// ---------------------------------------------------------------------------
__global__ void k_update(const float* __restrict__ emas,
                         const float* __restrict__ logit_decay,
                         float* __restrict__ out_emas, int BT, int Kp) {
    __shared__ float bv[256];
    __shared__ int   bi[256];
    int t = threadIdx.x;
    bv[t] = (t < Kp) ? g_dots[t] : -CUDART_INF_F;
    bi[t] = t;
    __syncthreads();
    for (int off = 128; off > 0; off >>= 1) {
        if (t < off) {
            if (bv[t + off] > bv[t] || (bv[t + off] == bv[t] && bi[t + off] < bi[t])) {
                bv[t] = bv[t + off]; bi[t] = bi[t + off];
            }
        }
        __syncthreads();
    }
    int ks = bi[0];
    float dd = sigmoidf_(logit_decay[0]);
    float invBT = 1.0f / (float)BT;
    for (int d = t; d < DD; d += 256) {
        float mean = g_xsum[d] * invBT;
        out_emas[(size_t)ks * DD + d] = dd * emas[(size_t)ks * DD + d] + (1.0f - dd) * mean;
    }
}

// ---------------------------------------------------------------------------
extern "C" void kernel_launch(void* const* d_in, const int* in_sizes, int n_in,
                              void* d_out, int out_size) {
    const float* x           = (const float*)d_in[0];
    const float* emas        = (const float*)d_in[1];
    const float* log_tau     = (const float*)d_in[2];
    const float* log_blend   = (const float*)d_in[3];
    const float* logit_decay = (const float*)d_in[4];

    int BT = in_sizes[0] / DD;   // 16384
    int Kp = in_sizes[1] / DD;   // 256
    float* out_x    = (float*)d_out;
    float* out_emas = (float*)d_out + (size_t)in_sizes[0];

    k_proto_norm<<<Kp, 256>>>(emas);

    // big fused pass: sim GEMM + scale + gelu + column partials
    k_sim_fused<<<BT / MTILE, 256>>>(x, out_x, log_tau, log_blend, logit_decay);

    // tail: column sums -> dots -> argmax EMA update
    k_colsum_reduce<<<DD / 256, 256>>>();
    k_dots<<<(Kp + 3) / 4, 128>>>(Kp);
    int n4e = in_sizes[1] / 4;
    k_copy4<<<(n4e + 255) / 256, 256>>>((const float4*)emas, (float4*)out_emas, n4e);
    k_update<<<1, 256>>>(emas, logit_decay, out_emas, BT, Kp);
}

// round 8
// speedup vs baseline: 4.7334x; 1.0128x over previous
#include <cuda_runtime.h>
#include <cuda_bf16.h>
#include <cuda_pipeline_primitives.h>
#include <math.h>
#include <math_constants.h>
#include <cstdint>

// Fixed problem geometry (GELU2_5892695130299): x (4,4096,4096) f32, emas (256,4096) f32.
#define DD       4096
#define KP       256
#define MTILE    64        // rows per CTA (sim kernel)
#define KCH      32        // K chunk (bf16): 64B per row
#define NCH      (DD / KCH)
#define NCTA     256       // BT / MTILE
#define EPS_NRM  1e-12f
#define SQ2PI    0.7978845608028654f

// ---- device scratch (no allocations allowed) ----
__device__ float          g_pnorm[KP * DD];      // normalized prototypes fp32 (k_dots)
__device__ __nv_bfloat16  g_pnorm_bf[KP * DD];   // normalized prototypes bf16 (MMA B)
__device__ float          g_partials[NCTA * DD]; // per-CTA column-sum partials (4 MB)
__device__ float          g_xsum[DD];
__device__ float          g_dots[KP];

__device__ __forceinline__ float sigmoidf_(float v) { return 1.0f / (1.0f + expf(-v)); }
__device__ __forceinline__ float tanh_fast(float v) {
    float r; asm("tanh.approx.f32 %0, %1;" : "=f"(r) : "f"(v)); return r;
}
__device__ __forceinline__ float gelu_tanh(float y) {
    return 0.5f * y * (1.0f + tanh_fast(SQ2PI * (y + 0.044715f * y * y * y)));
}

__device__ __forceinline__ void mma16816(float* c, uint32_t a0, uint32_t a1,
                                         uint32_t a2, uint32_t a3,
                                         uint32_t b0, uint32_t b1) {
    asm volatile(
        "mma.sync.aligned.m16n8k16.row.col.f32.bf16.bf16.f32 "
        "{%0,%1,%2,%3}, {%4,%5,%6,%7}, {%8,%9}, {%0,%1,%2,%3};"
        : "+f"(c[0]), "+f"(c[1]), "+f"(c[2]), "+f"(c[3])
        : "r"(a0), "r"(a1), "r"(a2), "r"(a3), "r"(b0), "r"(b1));
}

// ---------------------------------------------------------------------------
// 1) Normalize prototypes -> fp32 and bf16 copies
// ---------------------------------------------------------------------------
__global__ void k_proto_norm(const float* __restrict__ emas) {
    __shared__ float red[256];
    int k = blockIdx.x;
    const float* row = emas + (size_t)k * DD;
    float s = 0.f;
    for (int d = threadIdx.x; d < DD; d += 256) { float v = row[d]; s += v * v; }
    red[threadIdx.x] = s; __syncthreads();
    for (int off = 128; off > 0; off >>= 1) {
        if (threadIdx.x < off) red[threadIdx.x] += red[threadIdx.x + off];
        __syncthreads();
    }
    float inv = 1.0f / fmaxf(sqrtf(red[0]), EPS_NRM);
    for (int d = threadIdx.x; d < DD; d += 256) {
        float v = row[d] * inv;
        g_pnorm[(size_t)k * DD + d]    = v;
        g_pnorm_bf[(size_t)k * DD + d] = __float2bfloat16(v);
    }
}

// ---------------------------------------------------------------------------
// 2) Fused kernel: HMMA sim-GEMM (64x256 tile) -> per-row scale -> GELU pass
//    over the same 64 rows, with per-CTA column sums folded into the GELU
//    loads (each thread exclusively owns columns c == tid (mod 256)).
// ---------------------------------------------------------------------------
__global__ __launch_bounds__(256, 2) void k_sim_fused(const float* __restrict__ x,
                                                      float* __restrict__ out_x,
                                                      const float* __restrict__ log_tau,
                                                      const float* __restrict__ log_blend,
                                                      const float* __restrict__ logit_decay) {
    __shared__ __align__(16) unsigned char smA[2][MTILE * 64];   //  8 KB
    __shared__ __align__(16) unsigned char smB[2][KP * 64];      // 32 KB

    const int tid  = threadIdx.x;
    const int w    = tid >> 5;
    const int lane = tid & 31;
    const int g    = lane >> 2;
    const int tg   = lane & 3;
    const int row0 = blockIdx.x * MTILE;
    const int arow = tid >> 2;
    const int apart = tid & 3;

    const float4* x4 = (const float4*)x;

    float acc[4][4][4];
    #pragma unroll
    for (int mt = 0; mt < 4; mt++)
        #pragma unroll
        for (int nt = 0; nt < 4; nt++)
            #pragma unroll
            for (int q = 0; q < 4; q++) acc[mt][nt][q] = 0.f;

    float nrm = 0.f;

    auto issueB = [&](int k0, int buf) {
        #pragma unroll
        for (int p = 0; p < 4; p++) {
            int n = (tid >> 2) + p * 64;
            unsigned char* dst = smB[buf] + n * 64 + ((apart ^ ((n >> 1) & 3)) * 16);
            const __nv_bfloat16* src = g_pnorm_bf + (size_t)n * DD + k0 + apart * 8;
            __pipeline_memcpy_async(dst, src, 16);
        }
    };
    auto ldgA = [&](int k0, float4& v0, float4& v1) {
        const float4* p = x4 + (size_t)(row0 + arow) * (DD / 4) + (k0 >> 2) + apart * 2;
        v0 = p[0]; v1 = p[1];
        nrm += v0.x * v0.x + v0.y * v0.y + v0.z * v0.z + v0.w * v0.w
             + v1.x * v1.x + v1.y * v1.y + v1.z * v1.z + v1.w * v1.w;
    };
    auto stsA = [&](int buf, const float4& v0, const float4& v1) {
        __nv_bfloat162 h0 = __floats2bfloat162_rn(v0.x, v0.y);
        __nv_bfloat162 h1 = __floats2bfloat162_rn(v0.z, v0.w);
        __nv_bfloat162 h2 = __floats2bfloat162_rn(v1.x, v1.y);
        __nv_bfloat162 h3 = __floats2bfloat162_rn(v1.z, v1.w);
        uint4* dst = (uint4*)(smA[buf] + arow * 64 + ((apart ^ ((arow >> 1) & 3)) * 16));
        *dst = make_uint4(*(uint32_t*)&h0, *(uint32_t*)&h1, *(uint32_t*)&h2, *(uint32_t*)&h3);
    };
    auto compute = [&](int buf) {
        const unsigned char* Ab = smA[buf];
        const unsigned char* Bb = smB[buf];
        #pragma unroll
        for (int ks = 0; ks < 2; ks++) {
            uint32_t b0[4], b1[4];
            #pragma unroll
            for (int nt = 0; nt < 4; nt++) {
                int n = w * 32 + nt * 8 + g;
                int s = (n >> 1) & 3;
                const unsigned char* base = Bb + n * 64;
                b0[nt] = *(const uint32_t*)(base + (((2 * ks)     ^ s) * 16) + 4 * tg);
                b1[nt] = *(const uint32_t*)(base + (((2 * ks + 1) ^ s) * 16) + 4 * tg);
            }
            #pragma unroll
            for (int mt = 0; mt < 4; mt++) {
                int r0r = mt * 16 + g, r1r = r0r + 8;
                int s0 = (r0r >> 1) & 3, s1 = (r1r >> 1) & 3;
                uint32_t a0 = *(const uint32_t*)(Ab + r0r * 64 + (((2 * ks)     ^ s0) * 16) + 4 * tg);
                uint32_t a1 = *(const uint32_t*)(Ab + r1r * 64 + (((2 * ks)     ^ s1) * 16) + 4 * tg);
                uint32_t a2 = *(const uint32_t*)(Ab + r0r * 64 + (((2 * ks + 1) ^ s0) * 16) + 4 * tg);
                uint32_t a3 = *(const uint32_t*)(Ab + r1r * 64 + (((2 * ks + 1) ^ s1) * 16) + 4 * tg);
                #pragma unroll
                for (int nt = 0; nt < 4; nt++)
                    mma16816(acc[mt][nt], a0, a1, a2, a3, b0[nt], b1[nt]);
            }
        }
    };

    // ---- prologue ----
    issueB(0, 0);
    __pipeline_commit();
    {
        float4 v0, v1;
        ldgA(0, v0, v1);
        stsA(0, v0, v1);
    }
    __pipeline_wait_prior(0);
    __syncthreads();

    // ---- main GEMM loop ----
    for (int ic = 0; ic < NCH; ic++) {
        int buf = ic & 1, nbuf = buf ^ 1;
        float4 nv0, nv1;
        if (ic < NCH - 1) {
            issueB((ic + 1) * KCH, nbuf);
            __pipeline_commit();
            ldgA((ic + 1) * KCH, nv0, nv1);
        }
        compute(buf);
        if (ic < NCH - 1) {
            stsA(nbuf, nv0, nv1);
            __pipeline_wait_prior(0);
        }
        __syncthreads();
    }

    // ---- epilogue: row max + row norm -> scale (smem scratch aliases smA) ----
    float* rowmax = (float*)smA;                          // 64*8 floats
    float* sc     = (float*)((unsigned char*)smA + 2048); // 64 floats (norms, then scale)

    nrm += __shfl_xor_sync(0xffffffffu, nrm, 1);
    nrm += __shfl_xor_sync(0xffffffffu, nrm, 2);
    if ((tid & 3) == 0) sc[arow] = nrm;

    #pragma unroll
    for (int mt = 0; mt < 4; mt++) {
        float m0 = -CUDART_INF_F, m1 = -CUDART_INF_F;
        #pragma unroll
        for (int nt = 0; nt < 4; nt++) {
            m0 = fmaxf(m0, fmaxf(acc[mt][nt][0], acc[mt][nt][1]));
            m1 = fmaxf(m1, fmaxf(acc[mt][nt][2], acc[mt][nt][3]));
        }
        m0 = fmaxf(m0, __shfl_xor_sync(0xffffffffu, m0, 1));
        m0 = fmaxf(m0, __shfl_xor_sync(0xffffffffu, m0, 2));
        m1 = fmaxf(m1, __shfl_xor_sync(0xffffffffu, m1, 1));
        m1 = fmaxf(m1, __shfl_xor_sync(0xffffffffu, m1, 2));
        if (tg == 0) {
            rowmax[(mt * 16 + g) * 8 + w]     = m0;
            rowmax[(mt * 16 + 8 + g) * 8 + w] = m1;
        }
    }
    __syncthreads();

    if (tid < MTILE) {
        float m = rowmax[tid * 8];
        #pragma unroll
        for (int j = 1; j < 8; j++) m = fmaxf(m, rowmax[tid * 8 + j]);
        float inv = 1.0f / fmaxf(sqrtf(sc[tid]), EPS_NRM);
        float tau = expf(log_tau[0]);
        float ad_ = sigmoidf_(log_blend[0]) * sigmoidf_(logit_decay[0]);
        sc[tid] = 1.0f - ad_ + ad_ * expf(-tau * (m * inv));
    }
    __syncthreads();

    // ---- fused GELU + per-CTA column partial sums over this 64-row block ----
    // idx = tid + 256*j : thread exclusively owns float4 columns tid+256*(j&3).
    float cs[16];
    #pragma unroll
    for (int p = 0; p < 16; p++) cs[p] = 0.f;

    const float4* xr = x4 + (size_t)row0 * (DD / 4);
    float4* orow = (float4*)out_x + (size_t)row0 * (DD / 4);

    #pragma unroll 4
    for (int j = 0; j < 256; j++) {
        int idx = tid + j * 256;
        float4 v = xr[idx];
        int slot = (j & 3) * 4;
        cs[slot + 0] += v.x; cs[slot + 1] += v.y;
        cs[slot + 2] += v.z; cs[slot + 3] += v.w;
        float s = sc[idx >> 10];
        v.x = gelu_tanh(v.x * s);
        v.y = gelu_tanh(v.y * s);
        v.z = gelu_tanh(v.z * s);
        v.w = gelu_tanh(v.w * s);
        orow[idx] = v;
    }

    float4* gp = (float4*)(g_partials + (size_t)blockIdx.x * DD);
    #pragma unroll
    for (int slot = 0; slot < 4; slot++)
        gp[tid + 256 * slot] = make_float4(cs[slot * 4 + 0], cs[slot * 4 + 1],
                                           cs[slot * 4 + 2], cs[slot * 4 + 3]);
}

// ---------------------------------------------------------------------------
// 3) Reduce per-CTA column partials -> g_xsum (deterministic order)
// ---------------------------------------------------------------------------
__global__ void k_colsum_reduce() {
    int col = blockIdx.x * 256 + threadIdx.x;
    float s = 0.f;
    for (int rb = 0; rb < NCTA; rb++) s += g_partials[(size_t)rb * DD + col];
    g_xsum[col] = s;
}

// ---------------------------------------------------------------------------
// 4) dots[k] = p_norm[k] . x_sum  (float4, one warp per k)
// ---------------------------------------------------------------------------
__global__ void k_dots(int Kp) {
    int warp = threadIdx.x >> 5, lane = threadIdx.x & 31;
    int k = blockIdx.x * 4 + warp;
    if (k >= Kp) return;
    const float4* pr = (const float4*)(g_pnorm + (size_t)k * DD);
    const float4* xs = (const float4*)g_xsum;
    float s = 0.f;
    #pragma unroll 4
    for (int d = lane; d < DD / 4; d += 32) {
        float4 a = pr[d], b = xs[d];
        s += a.x * b.x + a.y * b.y + a.z * b.z + a.w * b.w;
    }
    #pragma unroll
    for (int off = 16; off; off >>= 1) s += __shfl_xor_sync(0xffffffffu, s, off);
    if (lane == 0) g_dots[k] = s;
}

// ---------------------------------------------------------------------------
// 5) Copy emas -> output emas region
// ---------------------------------------------------------------------------
__global__ void k_copy4(const float4* __restrict__ src, float4* __restrict__ dst, int n4) {
    int i = blockIdx.x * blockDim.x + threadIdx.x;
    if (i < n4) dst[i] = src[i];
}

// ---------------------------------------------------------------------------
// 6) argmax(dots) + EMA row update
// ---------------------------------------------------------------------------
__global__ void k_update(const float* __restrict__ emas,
                         const float* __restrict__ logit_decay,
                         float* __restrict__ out_emas, int BT, int Kp) {
    __shared__ float bv[256];
    __shared__ int   bi[256];
    int t = threadIdx.x;
    bv[t] = (t < Kp) ? g_dots[t] : -CUDART_INF_F;
    bi[t] = t;
    __syncthreads();
    for (int off = 128; off > 0; off >>= 1) {
        if (t < off) {
            if (bv[t + off] > bv[t] || (bv[t + off] == bv[t] && bi[t + off] < bi[t])) {
                bv[t] = bv[t + off]; bi[t] = bi[t + off];
            }
        }
        __syncthreads();
    }
    int ks = bi[0];
    float dd = sigmoidf_(logit_decay[0]);
    float invBT = 1.0f / (float)BT;
    for (int d = t; d < DD; d += 256) {
        float mean = g_xsum[d] * invBT;
        out_emas[(size_t)ks * DD + d] = dd * emas[(size_t)ks * DD + d] + (1.0f - dd) * mean;
    }
}

// ---------------------------------------------------------------------------
extern "C" void kernel_launch(void* const* d_in, const int* in_sizes, int n_in,
                              void* d_out, int out_size) {
    const float* x           = (const float*)d_in[0];
    const float* emas        = (const float*)d_in[1];
    const float* log_tau     = (const float*)d_in[2];
    const float* log_blend   = (const float*)d_in[3];
    const float* logit_decay = (const float*)d_in[4];

    int BT = in_sizes[0] / DD;   // 16384
    int Kp = in_sizes[1] / DD;   // 256
    float* out_x    = (float*)d_out;
    float* out_emas = (float*)d_out + (size_t)in_sizes[0];

    k_proto_norm<<<Kp, 256>>>(emas);

    // big fused pass: sim GEMM + scale + gelu + column partials
    k_sim_fused<<<BT / MTILE, 256>>>(x, out_x, log_tau, log_blend, logit_decay);

    // tail: column sums -> dots -> argmax EMA update
    k_colsum_reduce<<<DD / 256, 256>>>();
    k_dots<<<(Kp + 3) / 4, 128>>>(Kp);
    int n4e = in_sizes[1] / 4;
    k_copy4<<<(n4e + 255) / 256, 256>>>((const float4*)emas, (float4*)out_emas, n4e);
    k_update<<<1, 256>>>(emas, logit_decay, out_emas, BT, Kp);
}